// round 7
// baseline (speedup 1.0000x reference)
#include <cuda_runtime.h>
#include <cuda_bf16.h>
#include <cstdint>

#define S_LEN 2048
#define HEADS 8
#define BATCH 2
#define DHEAD 128
#define BM 256
#define BN 64
#define NJT (S_LEN / BN)
#define THREADS 256

// smem byte regions (tiles: row stride 256B = 128 bf16 cols)
#define SM_QHI 0
#define SM_QLO 65536
#define SM_K 131072  // + buf*32768 : hi, +16384 : lo
#define SM_V 196608  // hi, +16384 : lo
#define SMEM_TOTAL 229376

__device__ float g_rnorm[HEADS * S_LEN];

__device__ __forceinline__ uint32_t smem_u32(const void* p) {
    uint32_t a;
    asm("{ .reg .u64 t; cvta.to.shared.u64 t, %1; cvt.u32.u64 %0, t; }" : "=r"(a) : "l"(p));
    return a;
}

// pack (e0,e1) -> bf16x2 hi (lo-half=e0), residual bf16x2 lo
__device__ __forceinline__ void split2(float e0, float e1, uint32_t& hi, uint32_t& lo) {
    asm("cvt.rn.bf16x2.f32 %0, %1, %2;" : "=r"(hi) : "f"(e1), "f"(e0));
    float f0 = __uint_as_float(hi << 16);
    float f1 = __uint_as_float(hi & 0xffff0000u);
    asm("cvt.rn.bf16x2.f32 %0, %1, %2;" : "=r"(lo) : "f"(e1 - f1), "f"(e0 - f0));
}

__device__ __forceinline__ void ldmx4(uint32_t& r0, uint32_t& r1, uint32_t& r2, uint32_t& r3,
                                      uint32_t a) {
    asm volatile("ldmatrix.sync.aligned.m8n8.x4.shared.b16 {%0,%1,%2,%3}, [%4];"
                 : "=r"(r0), "=r"(r1), "=r"(r2), "=r"(r3) : "r"(a));
}
__device__ __forceinline__ void ldmx4t(uint32_t& r0, uint32_t& r1, uint32_t& r2, uint32_t& r3,
                                       uint32_t a) {
    asm volatile("ldmatrix.sync.aligned.m8n8.x4.trans.shared.b16 {%0,%1,%2,%3}, [%4];"
                 : "=r"(r0), "=r"(r1), "=r"(r2), "=r"(r3) : "r"(a));
}

__device__ __forceinline__ void mmab(float* c, const uint32_t* a, uint32_t b0, uint32_t b1) {
    asm volatile(
        "mma.sync.aligned.m16n8k16.row.col.f32.bf16.bf16.f32 "
        "{%0,%1,%2,%3},{%4,%5,%6,%7},{%8,%9},{%0,%1,%2,%3};"
        : "+f"(c[0]), "+f"(c[1]), "+f"(c[2]), "+f"(c[3])
        : "r"(a[0]), "r"(a[1]), "r"(a[2]), "r"(a[3]), "r"(b0), "r"(b1));
}

// ---------------- rnorm: rsqrt(sum_j omask[h,i,j]) ----------------
__global__ void rnorm_kernel(const float* __restrict__ omask) {
    int row = blockIdx.x;
    const float* p = omask + (size_t)row * S_LEN;
    float s = 0.f;
    for (int j = threadIdx.x * 4; j < S_LEN; j += 256 * 4) {
        float4 f = *(const float4*)(p + j);
        s += f.x + f.y + f.z + f.w;
    }
#pragma unroll
    for (int off = 16; off > 0; off >>= 1) s += __shfl_xor_sync(0xffffffffu, s, off);
    __shared__ float red[8];
    if ((threadIdx.x & 31) == 0) red[threadIdx.x >> 5] = s;
    __syncthreads();
    if (threadIdx.x == 0) {
        float t = 0.f;
#pragma unroll
        for (int i = 0; i < 8; i++) t += red[i];
        g_rnorm[row] = (t > 0.f) ? rsqrtf(t) : 0.f;
    }
}

// direct LDG->split->STS of a 64x128 fp32 tile into hi/lo bf16 smem (swizzled)
__device__ __forceinline__ void load_tile(const float* __restrict__ src, char* hi, char* lo,
                                          int tid) {
#pragma unroll
    for (int i = 0; i < 8; i++) {
        int x = tid + i * THREADS;
        int r = x >> 5, c4 = (x & 31) << 2;
        float4 f = *(const float4*)(src + r * DHEAD + c4);
        uint32_t h0, l0, h1, l1;
        split2(f.x, f.y, h0, l0);
        split2(f.z, f.w, h1, l1);
        int off = r * 256 + ((((c4 >> 3)) ^ (r & 7)) << 4) + (c4 & 7) * 2;
        *(uint2*)(hi + off) = make_uint2(h0, h1);
        *(uint2*)(lo + off) = make_uint2(l0, l1);
    }
}

__global__ __launch_bounds__(THREADS, 1)
void retention_mma_kernel(const float* __restrict__ q, const float* __restrict__ k,
                          const float* __restrict__ v, const float* __restrict__ omask,
                          float* __restrict__ out) {
    extern __shared__ char smc[];
    const uint32_t su = smem_u32(smc);
    const int tid = threadIdx.x;
    const int wid = tid >> 5, lane = tid & 31;
    const int m0 = wid * 32;
    const int g = lane >> 2;

    const int it = blockIdx.x, h = blockIdx.y, b = blockIdx.z;
    const int i0 = it * BM;
    const size_t bh = (size_t)(b * HEADS + h);
    const float* qbase = q + (bh * S_LEN + i0) * DHEAD;
    const float* kbase = k + bh * S_LEN * DHEAD;
    const float* vbase = v + bh * S_LEN * DHEAD;
    const float* mbase = omask + ((size_t)h * S_LEN + i0) * S_LEN;

    // ---- Q tile [256x128] -> bf16 hi/lo ----
#pragma unroll 4
    for (int x = tid; x < 256 * 32; x += THREADS) {
        int r = x >> 5, c4 = (x & 31) << 2;
        float4 f = *(const float4*)(qbase + r * DHEAD + c4);
        uint32_t h0, l0, h1, l1;
        split2(f.x, f.y, h0, l0);
        split2(f.z, f.w, h1, l1);
        int off = r * 256 + ((((c4 >> 3)) ^ (r & 7)) << 4) + (c4 & 7) * 2;
        *(uint2*)(smc + SM_QHI + off) = make_uint2(h0, h1);
        *(uint2*)(smc + SM_QLO + off) = make_uint2(l0, l1);
    }
    load_tile(kbase, smc + SM_K, smc + SM_K + 16384, tid);
    load_tile(vbase, smc + SM_V, smc + SM_V + 16384, tid);

    float rn[2][2];
#pragma unroll
    for (int mt = 0; mt < 2; mt++) {
        rn[mt][0] = g_rnorm[h * S_LEN + i0 + m0 + mt * 16 + g];
        rn[mt][1] = g_rnorm[h * S_LEN + i0 + m0 + mt * 16 + g + 8];
    }

    float oacc[2][16][4];
#pragma unroll
    for (int mt = 0; mt < 2; mt++)
#pragma unroll
        for (int nt = 0; nt < 16; nt++)
#pragma unroll
            for (int e = 0; e < 4; e++) oacc[mt][nt][e] = 0.f;

    const int krow_b = (lane & 7) + ((lane >> 4) << 3);
    const int qrow0 = m0 + (lane & 15);

    __syncthreads();

    for (int jt = 0; jt < NJT; jt++) {
        const int buf = jt & 1;
        const bool pf = (jt + 1 < NJT);
        const uint32_t khb = su + SM_K + buf * 32768, klb = khb + 16384;
        const uint32_t vhb = su + SM_V, vlb = vhb + 16384;

        // ================= HALF A (j 0..31) =================
        // mask prefetch (rn folded)
        float2 mk0[2][4], mk1[2][4];
#pragma unroll
        for (int mt = 0; mt < 2; mt++) {
            const float* mp =
                mbase + (size_t)(m0 + mt * 16 + g) * S_LEN + jt * BN + (lane & 3) * 2;
#pragma unroll
            for (int nt = 0; nt < 4; nt++) {
                float2 t0 = *(const float2*)(mp + nt * 8);
                float2 t1 = *(const float2*)(mp + 8 * S_LEN + nt * 8);
                mk0[mt][nt] = make_float2(t0.x * rn[mt][0], t0.y * rn[mt][0]);
                mk1[mt][nt] = make_float2(t1.x * rn[mt][1], t1.y * rn[mt][1]);
            }
        }
        // K LDG (next tile)
        float4 kreg[8];
        if (pf) {
            const float* kbn = kbase + (size_t)(jt + 1) * BN * DHEAD;
#pragma unroll
            for (int i = 0; i < 8; i++) {
                int x = tid + i * THREADS;
                kreg[i] = *(const float4*)(kbn + (x >> 5) * DHEAD + ((x & 31) << 2));
            }
        }

        // GEMM1a: np 0..1
        float sacc[2][4][4];
#pragma unroll
        for (int mt = 0; mt < 2; mt++)
#pragma unroll
            for (int nt = 0; nt < 4; nt++)
#pragma unroll
                for (int e = 0; e < 4; e++) sacc[mt][nt][e] = 0.f;
#pragma unroll
        for (int ks = 0; ks < 8; ks++) {
            uint32_t qh[2][4], ql[2][4];
#pragma unroll
            for (int mt = 0; mt < 2; mt++) {
                int qrow = qrow0 + mt * 16;
                uint32_t qoff = qrow * 256 + (((2 * ks + (lane >> 4)) ^ (qrow & 7)) << 4);
                ldmx4(qh[mt][0], qh[mt][1], qh[mt][2], qh[mt][3], su + SM_QHI + qoff);
                ldmx4(ql[mt][0], ql[mt][1], ql[mt][2], ql[mt][3], su + SM_QLO + qoff);
            }
#pragma unroll
            for (int np = 0; np < 2; np++) {
                int krow = np * 16 + krow_b;
                uint32_t koff =
                    krow * 256 + (((2 * ks + ((lane >> 3) & 1)) ^ (krow & 7)) << 4);
                uint32_t h0, h1, h2, h3, l0, l1, l2, l3;
                ldmx4(h0, h1, h2, h3, khb + koff);
                ldmx4(l0, l1, l2, l3, klb + koff);
#pragma unroll
                for (int mt = 0; mt < 2; mt++) {
                    mmab(sacc[mt][2 * np], qh[mt], h0, h1);
                    mmab(sacc[mt][2 * np + 1], qh[mt], h2, h3);
                    mmab(sacc[mt][2 * np], qh[mt], l0, l1);
                    mmab(sacc[mt][2 * np + 1], qh[mt], l2, l3);
                    mmab(sacc[mt][2 * np], ql[mt], h0, h1);
                    mmab(sacc[mt][2 * np + 1], ql[mt], h2, h3);
                }
            }
        }
        // K split+STS (LDG long done)
        if (pf) {
            char* khn = smc + SM_K + (buf ^ 1) * 32768;
#pragma unroll
            for (int i = 0; i < 8; i++) {
                int x = tid + i * THREADS;
                int r = x >> 5, c4 = (x & 31) << 2;
                uint32_t h0, l0, h1, l1;
                split2(kreg[i].x, kreg[i].y, h0, l0);
                split2(kreg[i].z, kreg[i].w, h1, l1);
                int off = r * 256 + ((((c4 >> 3)) ^ (r & 7)) << 4) + (c4 & 7) * 2;
                *(uint2*)(khn + off) = make_uint2(h0, h1);
                *(uint2*)(khn + 16384 + off) = make_uint2(l0, l1);
            }
        }
        // epi A
#pragma unroll
        for (int mt = 0; mt < 2; mt++)
#pragma unroll
            for (int nt = 0; nt < 4; nt++) {
                sacc[mt][nt][0] *= mk0[mt][nt].x;
                sacc[mt][nt][1] *= mk0[mt][nt].y;
                sacc[mt][nt][2] *= mk1[mt][nt].x;
                sacc[mt][nt][3] *= mk1[mt][nt].y;
            }
        // GEMM2 A: kt 0..1
#pragma unroll
        for (int ktl = 0; ktl < 2; ktl++) {
            uint32_t ah[2][4], al[2][4];
#pragma unroll
            for (int mt = 0; mt < 2; mt++) {
                split2(sacc[mt][2 * ktl][0], sacc[mt][2 * ktl][1], ah[mt][0], al[mt][0]);
                split2(sacc[mt][2 * ktl][2], sacc[mt][2 * ktl][3], ah[mt][1], al[mt][1]);
                split2(sacc[mt][2 * ktl + 1][0], sacc[mt][2 * ktl + 1][1], ah[mt][2], al[mt][2]);
                split2(sacc[mt][2 * ktl + 1][2], sacc[mt][2 * ktl + 1][3], ah[mt][3], al[mt][3]);
            }
            const int vrow = ktl * 16 + (lane & 15);
#pragma unroll
            for (int np = 0; np < 8; np++) {
                uint32_t voff = vrow * 256 + (((2 * np + (lane >> 4)) ^ (vrow & 7)) << 4);
                uint32_t h0, h1, h2, h3, l0, l1, l2, l3;
                ldmx4t(h0, h1, h2, h3, vhb + voff);
                ldmx4t(l0, l1, l2, l3, vlb + voff);
#pragma unroll
                for (int mt = 0; mt < 2; mt++) {
                    mmab(oacc[mt][2 * np], ah[mt], h0, h1);
                    mmab(oacc[mt][2 * np + 1], ah[mt], h2, h3);
                    mmab(oacc[mt][2 * np], ah[mt], l0, l1);
                    mmab(oacc[mt][2 * np + 1], ah[mt], l2, l3);
                    mmab(oacc[mt][2 * np], al[mt], h0, h1);
                    mmab(oacc[mt][2 * np + 1], al[mt], h2, h3);
                }
            }
        }

        // ================= HALF B (j 32..63) =================
#pragma unroll
        for (int mt = 0; mt < 2; mt++) {
            const float* mp =
                mbase + (size_t)(m0 + mt * 16 + g) * S_LEN + jt * BN + 32 + (lane & 3) * 2;
#pragma unroll
            for (int nt = 0; nt < 4; nt++) {
                float2 t0 = *(const float2*)(mp + nt * 8);
                float2 t1 = *(const float2*)(mp + 8 * S_LEN + nt * 8);
                mk0[mt][nt] = make_float2(t0.x * rn[mt][0], t0.y * rn[mt][0]);
                mk1[mt][nt] = make_float2(t1.x * rn[mt][1], t1.y * rn[mt][1]);
            }
        }
        // V LDG (next tile)
        float4 vreg[8];
        if (pf) {
            const float* vbn = vbase + (size_t)(jt + 1) * BN * DHEAD;
#pragma unroll
            for (int i = 0; i < 8; i++) {
                int x = tid + i * THREADS;
                vreg[i] = *(const float4*)(vbn + (x >> 5) * DHEAD + ((x & 31) << 2));
            }
        }
        // GEMM1b: np 2..3
#pragma unroll
        for (int mt = 0; mt < 2; mt++)
#pragma unroll
            for (int nt = 0; nt < 4; nt++)
#pragma unroll
                for (int e = 0; e < 4; e++) sacc[mt][nt][e] = 0.f;
#pragma unroll
        for (int ks = 0; ks < 8; ks++) {
            uint32_t qh[2][4], ql[2][4];
#pragma unroll
            for (int mt = 0; mt < 2; mt++) {
                int qrow = qrow0 + mt * 16;
                uint32_t qoff = qrow * 256 + (((2 * ks + (lane >> 4)) ^ (qrow & 7)) << 4);
                ldmx4(qh[mt][0], qh[mt][1], qh[mt][2], qh[mt][3], su + SM_QHI + qoff);
                ldmx4(ql[mt][0], ql[mt][1], ql[mt][2], ql[mt][3], su + SM_QLO + qoff);
            }
#pragma unroll
            for (int np = 0; np < 2; np++) {
                int krow = (np + 2) * 16 + krow_b;
                uint32_t koff =
                    krow * 256 + (((2 * ks + ((lane >> 3) & 1)) ^ (krow & 7)) << 4);
                uint32_t h0, h1, h2, h3, l0, l1, l2, l3;
                ldmx4(h0, h1, h2, h3, khb + koff);
                ldmx4(l0, l1, l2, l3, klb + koff);
#pragma unroll
                for (int mt = 0; mt < 2; mt++) {
                    mmab(sacc[mt][2 * np], qh[mt], h0, h1);
                    mmab(sacc[mt][2 * np + 1], qh[mt], h2, h3);
                    mmab(sacc[mt][2 * np], qh[mt], l0, l1);
                    mmab(sacc[mt][2 * np + 1], qh[mt], l2, l3);
                    mmab(sacc[mt][2 * np], ql[mt], h0, h1);
                    mmab(sacc[mt][2 * np + 1], ql[mt], h2, h3);
                }
            }
        }
        // epi B
#pragma unroll
        for (int mt = 0; mt < 2; mt++)
#pragma unroll
            for (int nt = 0; nt < 4; nt++) {
                sacc[mt][nt][0] *= mk0[mt][nt].x;
                sacc[mt][nt][1] *= mk0[mt][nt].y;
                sacc[mt][nt][2] *= mk1[mt][nt].x;
                sacc[mt][nt][3] *= mk1[mt][nt].y;
            }
        // GEMM2 B: kt 2..3
#pragma unroll
        for (int ktl = 0; ktl < 2; ktl++) {
            uint32_t ah[2][4], al[2][4];
#pragma unroll
            for (int mt = 0; mt < 2; mt++) {
                split2(sacc[mt][2 * ktl][0], sacc[mt][2 * ktl][1], ah[mt][0], al[mt][0]);
                split2(sacc[mt][2 * ktl][2], sacc[mt][2 * ktl][3], ah[mt][1], al[mt][1]);
                split2(sacc[mt][2 * ktl + 1][0], sacc[mt][2 * ktl + 1][1], ah[mt][2], al[mt][2]);
                split2(sacc[mt][2 * ktl + 1][2], sacc[mt][2 * ktl + 1][3], ah[mt][3], al[mt][3]);
            }
            const int vrow = (ktl + 2) * 16 + (lane & 15);
#pragma unroll
            for (int np = 0; np < 8; np++) {
                uint32_t voff = vrow * 256 + (((2 * np + (lane >> 4)) ^ (vrow & 7)) << 4);
                uint32_t h0, h1, h2, h3, l0, l1, l2, l3;
                ldmx4t(h0, h1, h2, h3, vhb + voff);
                ldmx4t(l0, l1, l2, l3, vlb + voff);
#pragma unroll
                for (int mt = 0; mt < 2; mt++) {
                    mmab(oacc[mt][2 * np], ah[mt], h0, h1);
                    mmab(oacc[mt][2 * np + 1], ah[mt], h2, h3);
                    mmab(oacc[mt][2 * np], ah[mt], l0, l1);
                    mmab(oacc[mt][2 * np + 1], ah[mt], l2, l3);
                    mmab(oacc[mt][2 * np], al[mt], h0, h1);
                    mmab(oacc[mt][2 * np + 1], al[mt], h2, h3);
                }
            }
        }

        // ---- rotate V buffer ----
        __syncthreads();
        if (pf) {
            char* vh = smc + SM_V;
#pragma unroll
            for (int i = 0; i < 8; i++) {
                int x = tid + i * THREADS;
                int r = x >> 5, c4 = (x & 31) << 2;
                uint32_t h0, l0, h1, l1;
                split2(vreg[i].x, vreg[i].y, h0, l0);
                split2(vreg[i].z, vreg[i].w, h1, l1);
                int off = r * 256 + ((((c4 >> 3)) ^ (r & 7)) << 4) + (c4 & 7) * 2;
                *(uint2*)(vh + off) = make_uint2(h0, h1);
                *(uint2*)(vh + 16384 + off) = make_uint2(l0, l1);
            }
        }
        __syncthreads();
    }

    // ---- RMSNorm (warp-local rows) + store ----
#pragma unroll
    for (int mt = 0; mt < 2; mt++) {
        float p0 = 0.f, p1 = 0.f;
#pragma unroll
        for (int nt = 0; nt < 16; nt++) {
            p0 += oacc[mt][nt][0] * oacc[mt][nt][0] + oacc[mt][nt][1] * oacc[mt][nt][1];
            p1 += oacc[mt][nt][2] * oacc[mt][nt][2] + oacc[mt][nt][3] * oacc[mt][nt][3];
        }
        p0 += __shfl_xor_sync(0xffffffffu, p0, 1);
        p0 += __shfl_xor_sync(0xffffffffu, p0, 2);
        p1 += __shfl_xor_sync(0xffffffffu, p1, 1);
        p1 += __shfl_xor_sync(0xffffffffu, p1, 2);
        float sc0 = rsqrtf(p0 * (1.f / 128.f) + 1e-6f);
        float sc1 = rsqrtf(p1 * (1.f / 128.f) + 1e-6f);
        float* o0 = out + (bh * S_LEN + i0 + m0 + mt * 16 + g) * DHEAD + (lane & 3) * 2;
        float* o1 = o0 + 8 * DHEAD;
#pragma unroll
        for (int nt = 0; nt < 16; nt++) {
            *(float2*)(o0 + nt * 8) = make_float2(oacc[mt][nt][0] * sc0, oacc[mt][nt][1] * sc0);
            *(float2*)(o1 + nt * 8) = make_float2(oacc[mt][nt][2] * sc1, oacc[mt][nt][3] * sc1);
        }
    }
}

extern "C" void kernel_launch(void* const* d_in, const int* in_sizes, int n_in,
                              void* d_out, int out_size) {
    const float* q = (const float*)d_in[0];
    const float* k = (const float*)d_in[1];
    const float* v = (const float*)d_in[2];
    const float* omask = (const float*)d_in[3];
    float* out = (float*)d_out;

    cudaFuncSetAttribute(retention_mma_kernel, cudaFuncAttributeMaxDynamicSharedMemorySize,
                         SMEM_TOTAL);

    rnorm_kernel<<<HEADS * S_LEN, 256>>>(omask);
    retention_mma_kernel<<<dim3(S_LEN / BM, HEADS, BATCH), THREADS, SMEM_TOTAL>>>(
        q, k, v, omask, out);
}